// round 10
// baseline (speedup 1.0000x reference)
#include <cuda_runtime.h>

#define BB 4096
#define TT 1024
#define NN 16
#define NPT 2   // packed pairs per thread: 4 threads/row * 2 pairs * 2 = 16 filters
#define TQ (TT / 4)

// Quad-packed transposed currents: g_cur4[tq][b] = {cur[4tq..4tq+3]} for row b.
__device__ float4 g_cur4[(TQ + 4) * BB];

typedef unsigned long long u64;

__device__ __forceinline__ u64 pk2(float x, float y) {
    u64 r; asm("mov.b64 %0, {%1, %2};" : "=l"(r) : "f"(x), "f"(y)); return r;
}
__device__ __forceinline__ void upk2(u64 a, float& x, float& y) {
    asm("mov.b64 {%0, %1}, %2;" : "=f"(x), "=f"(y) : "l"(a));
}
__device__ __forceinline__ u64 fma2_(u64 a, u64 b, u64 c) {
    u64 d; asm("fma.rn.f32x2 %0, %1, %2, %3;" : "=l"(d) : "l"(a), "l"(b), "l"(c)); return d;
}
__device__ __forceinline__ u64 mul2_(u64 a, u64 b) {
    u64 d; asm("mul.rn.f32x2 %0, %1, %2;" : "=l"(d) : "l"(a), "l"(b)); return d;
}
__device__ __forceinline__ float tanh_a(float x) {
    float y; asm("tanh.approx.f32 %0, %1;" : "=f"(y) : "f"(x)); return y;
}

// ---------------------------------------------------------------------------
// Pass 1: transpose + quad-pack currents (B,T) -> g_cur4 (T/4, B) float4.
// ---------------------------------------------------------------------------
__global__ void transpose_kernel(const float* __restrict__ cur) {
    __shared__ float tile[32][33];
    const int tx = threadIdx.x, ty = threadIdx.y;
    const int t0 = blockIdx.x * 32, b0 = blockIdx.y * 32;
#pragma unroll
    for (int i = 0; i < 32; i += 8)
        tile[ty + i][tx] = cur[(size_t)(b0 + ty + i) * TT + (t0 + tx)];
    __syncthreads();
    float4 val;
    val.x = tile[tx][4 * ty + 0];
    val.y = tile[tx][4 * ty + 1];
    val.z = tile[tx][4 * ty + 2];
    val.w = tile[tx][4 * ty + 3];
    g_cur4[(size_t)((t0 >> 2) + ty) * BB + (b0 + tx)] = val;
}

// ---------------------------------------------------------------------------
// Pass 2: recurrence, moment pipeline (R9), with the cross-lane reduction
// done by WARP-PRIVATE VOLATILE SMEM EXCHANGE instead of shfl.sync.
//
// Why: shfl.sync carries a convergence envelope (WARPSYNC ~23cyc) + 26cyc
// SHFL; two per step ~ the unexplained ~90cyc/step residual that survived
// every other ablation. The body is branch-free => warp provably convergent
// => same-warp smem RAW is ordered by the in-order MIO queue. volatile pins
// STS(t) < LDS(t) < STS(t+1) program order. The th-chain executes between
// STS and LDS, hiding the 29cyc LDS latency; the moment-pipeline slack
// (R3 -> M2 -> M1 -> x, ~2 steps) absorbs the rest.
//
// Everything else from R9: M_k pipeline, packed f32x2 filters, quad LDG,
// lane-owned quad STG, csN folded into state, th-carried, tanh∘relu.
// ---------------------------------------------------------------------------
__global__ void __launch_bounds__(128, 1) gfr_kernel(
    const float* __restrict__ a, const float* __restrict__ b,
    const float* __restrict__ pc, const float* __restrict__ gb,
    const float* __restrict__ ds, const float* __restrict__ mc,
    const float* __restrict__ mfr, float* __restrict__ out)
{
    __shared__ volatile float xch[128];

    const int tid = threadIdx.x;
    const int sub = tid & 3;
    const int grp = tid & ~3;                 // base lane of this row's group
    const int row = blockIdx.x * 32 + (tid >> 2);
    const int f0  = sub * 4;

    const float MFR = mfr[0];
    const float invmc = 1.f / mc[0];
    const float csN = invmc * (1.f / (float)NN);

    u64 av[NPT], bv[NPT], dv[NPT], d3v[NPT], v[NPT];
#pragma unroll
    for (int i = 0; i < NPT; i++) {
        const float dA = 1.f - ds[f0 + 2 * i], dB = 1.f - ds[f0 + 2 * i + 1];
        av[i]  = pk2(csN * a[f0 + 2 * i], csN * a[f0 + 2 * i + 1]);
        bv[i]  = pk2(csN * 1000.f * MFR * b[f0 + 2 * i],
                     csN * 1000.f * MFR * b[f0 + 2 * i + 1]);
        dv[i]  = pk2(dA, dB);
        d3v[i] = pk2(dA * dA * dA, dB * dB * dB);
        v[i] = 0ull;
    }
    float suma = 0.f, sumb = 0.f, a1c = 0.f, b1c = 0.f, a2c = 0.f, b2c = 0.f;
#pragma unroll
    for (int n = 0; n < NN; n++) {
        const float dn = 1.f - ds[n];
        const float An = csN * a[n];
        const float Bn = csN * 1000.f * MFR * b[n];
        suma += a[n]; sumb += b[n];
        a1c += dn * An;        b1c += dn * Bn;
        a2c += dn * dn * An;   b2c += dn * dn * Bn;
    }
    const float ca = suma * csN;
    const float cb = 1000.f * MFR * sumb * csN;
    const float c0 = -gb[0] * invmc;
    const float q0 = pc[0] * pc[0], q1 = pc[1] * pc[1], q2 = pc[2] * pc[2],
                q3 = pc[3] * pc[3], q4 = pc[4] * pc[4];

    const float4* cp4 = g_cur4 + row;
    float* op = out + row + (size_t)sub * BB;
    float th = 0.f, M1 = 0.f, M2 = 0.f;

    float4 q0buf = __ldg(cp4);
    float4 q1buf = __ldg(cp4 + BB);

#define STEP(CUR, J)                                                        \
    {                                                                       \
        const float cur_ = (CUR);                                           \
        const float pre_ = fmaf(cur_, ca, c0);                              \
        /* own d^3 partial from state V[t-1]; publish to smem */            \
        u64 s_ = fma2_(d3v[1], v[1], mul2_(d3v[0], v[0]));                  \
        float sx_, sy_; upk2(s_, sx_, sy_);                                 \
        xch[tid] = sx_ + sy_;            /* STS (ordered before LDS) */     \
        /* ---- th critical path (uses carried M1 = M_1[t-1]) ---- */       \
        const float x_ = fmaf(th, cb, M1 + pre_);                           \
        const float x2_ = x_ * x_;                                          \
        const float u01_ = fmaf(q1, x_, q0);                                \
        const float u34_ = fmaf(q4, x_, q3);                                \
        const float w1s_ = fmaf(q2, x2_, u01_);                             \
        const float x3_ = x_ * x2_;                                         \
        float p_ = fmaf(u34_, x3_, w1s_);                                   \
        p_ = fmaxf(p_, 0.f);                                                \
        const float thn_ = tanh_a(p_);                                      \
        /* gather all 4 partials (broadcast LDS, no sync: same warp, */     \
        /* branch-free body => convergent; MIO queue is in-order)    */     \
        const float r0_ = xch[grp + 0];                                     \
        const float r1_ = xch[grp + 1];                                     \
        const float r2_ = xch[grp + 2];                                     \
        const float r3_ = xch[grp + 3];                                     \
        const float R3_ = (r0_ + r1_) + (r2_ + r3_);                        \
        /* ---- moment pipeline ---- */                                     \
        const float M1n_ = M2 + fmaf(th, b1c, cur_ * a1c);                  \
        const float M2n_ = R3_ + fmaf(th, b2c, cur_ * a2c);                 \
        /* ---- state update with OLD th ---- */                            \
        const u64 cur2_ = pk2(cur_, cur_);                                  \
        const u64 th2_  = pk2(th, th);                                      \
        v[0] = fma2_(dv[0], v[0], fma2_(th2_, bv[0], mul2_(cur2_, av[0]))); \
        v[1] = fma2_(dv[1], v[1], fma2_(th2_, bv[1], mul2_(cur2_, av[1]))); \
        M1 = M1n_; M2 = M2n_;                                               \
        if ((J) == sub) outv = MFR * thn_;                                  \
        th = thn_;                                                          \
    }

    for (int tq = 0; tq < TQ; tq += 2) {
        float outv = 0.f;
        {
            const float4 q = q0buf;
            q0buf = __ldg(cp4 + (size_t)(tq + 2) * BB);
            STEP(q.x, 0) STEP(q.y, 1) STEP(q.z, 2) STEP(q.w, 3)
            op[(size_t)tq * (4 * BB)] = outv;
        }
        {
            const float4 q = q1buf;
            q1buf = __ldg(cp4 + (size_t)(tq + 3) * BB);
            STEP(q.x, 0) STEP(q.y, 1) STEP(q.z, 2) STEP(q.w, 3)
            op[(size_t)(tq + 1) * (4 * BB)] = outv;
        }
    }
#undef STEP
}

extern "C" void kernel_launch(void* const* d_in, const int* in_sizes, int n_in,
                              void* d_out, int out_size) {
    const float* currents = (const float*)d_in[0];
    const float* a   = (const float*)d_in[1];
    const float* b   = (const float*)d_in[2];
    const float* pc  = (const float*)d_in[3];
    const float* gb  = (const float*)d_in[4];
    const float* ds  = (const float*)d_in[5];
    const float* mc  = (const float*)d_in[6];
    const float* mfr = (const float*)d_in[7];
    float* out = (float*)d_out;

    dim3 tb(32, 8), tg(TT / 32, BB / 32);
    transpose_kernel<<<tg, tb>>>(currents);
    gfr_kernel<<<(4 * BB) / 128, 128>>>(a, b, pc, gb, ds, mc, mfr, out);
}

// round 11
// speedup vs baseline: 1.0006x; 1.0006x over previous
#include <cuda_runtime.h>

#define BB 4096
#define TT 1024
#define NN 16
#define NPT 2   // packed pairs per thread: 4 threads/row * 2 pairs * 2 = 16 filters
#define TQ (TT / 4)

// Quad-packed transposed currents: g_cur4[tq][b] = {cur[4tq..4tq+3]} for row b.
__device__ float4 g_cur4[(TQ + 4) * BB];

typedef unsigned long long u64;

__device__ __forceinline__ u64 pk2(float x, float y) {
    u64 r; asm("mov.b64 %0, {%1, %2};" : "=l"(r) : "f"(x), "f"(y)); return r;
}
__device__ __forceinline__ void upk2(u64 a, float& x, float& y) {
    asm("mov.b64 {%0, %1}, %2;" : "=f"(x), "=f"(y) : "l"(a));
}
__device__ __forceinline__ u64 fma2_(u64 a, u64 b, u64 c) {
    u64 d; asm("fma.rn.f32x2 %0, %1, %2, %3;" : "=l"(d) : "l"(a), "l"(b), "l"(c)); return d;
}
__device__ __forceinline__ u64 mul2_(u64 a, u64 b) {
    u64 d; asm("mul.rn.f32x2 %0, %1, %2;" : "=l"(d) : "l"(a), "l"(b)); return d;
}
__device__ __forceinline__ u64 add2_(u64 a, u64 b) {
    u64 d; asm("add.rn.f32x2 %0, %1, %2;" : "=l"(d) : "l"(a), "l"(b)); return d;
}
__device__ __forceinline__ float tanh_a(float x) {
    float y; asm("tanh.approx.f32 %0, %1;" : "=f"(y) : "f"(x)); return y;
}
__device__ __forceinline__ unsigned smem_addr(const void* p) {
    unsigned r;
    asm("{ .reg .u64 t; cvta.to.shared.u64 t, %1; cvt.u32.u64 %0, t; }"
        : "=r"(r) : "l"(p));
    return r;
}

// ---------------------------------------------------------------------------
// Pass 1: transpose + quad-pack currents (B,T) -> g_cur4 (T/4, B) float4.
// ---------------------------------------------------------------------------
__global__ void transpose_kernel(const float* __restrict__ cur) {
    __shared__ float tile[32][33];
    const int tx = threadIdx.x, ty = threadIdx.y;
    const int t0 = blockIdx.x * 32, b0 = blockIdx.y * 32;
#pragma unroll
    for (int i = 0; i < 32; i += 8)
        tile[ty + i][tx] = cur[(size_t)(b0 + ty + i) * TT + (t0 + tx)];
    __syncthreads();
    float4 val;
    val.x = tile[tx][4 * ty + 0];
    val.y = tile[tx][4 * ty + 1];
    val.z = tile[tx][4 * ty + 2];
    val.w = tile[tx][4 * ty + 3];
    g_cur4[(size_t)((t0 >> 2) + ty) * BB + (b0 + tx)] = val;
}

// ---------------------------------------------------------------------------
// Pass 2: recurrence, moment pipeline, MICRO-OP DIET vs R9/R10:
//  * state substitution u_i = d_i^3 * V_i: reduction partial is just
//    add2(u0,u1) — no per-step d^3 weighting (the u-update recurrence is the
//    same shape: u = d*u + cur*(d^3*a') + th*(d^3*b')).
//  * cross-lane gather is ONE ld.shared.v4.f32 (16B-aligned group base)
//    instead of 4 LDS.32 / 2 shfl.sync: per-step MIO ops drop 5 -> 2.
//  * inline-asm STS/LDS (volatile float4 would be split by the compiler).
// Ordering: branch-free body => convergent warp; same-warp smem RAW is
// handled in-order by the LSU (validated bit-identical in R10).
// ---------------------------------------------------------------------------
__global__ void __launch_bounds__(128, 1) gfr_kernel(
    const float* __restrict__ a, const float* __restrict__ b,
    const float* __restrict__ pc, const float* __restrict__ gb,
    const float* __restrict__ ds, const float* __restrict__ mc,
    const float* __restrict__ mfr, float* __restrict__ out)
{
    __shared__ float xch[128];

    const int tid = threadIdx.x;
    const int sub = tid & 3;
    const int row = blockIdx.x * 32 + (tid >> 2);
    const int f0  = sub * 4;

    const unsigned xb  = smem_addr(xch);
    const unsigned ast = xb + tid * 4;             // this lane's slot
    const unsigned ald = xb + (tid & ~3) * 4;      // group base (16B aligned)

    const float MFR = mfr[0];
    const float invmc = 1.f / mc[0];
    const float csN = invmc * (1.f / (float)NN);

    // u-state constants: u = d*u + cur*(csN*d^3*a) + th*(csN*1000*MFR*d^3*b)
    u64 av[NPT], bv[NPT], dv[NPT], u[NPT];
#pragma unroll
    for (int i = 0; i < NPT; i++) {
        const float dA = 1.f - ds[f0 + 2 * i], dB = 1.f - ds[f0 + 2 * i + 1];
        const float dA3 = dA * dA * dA, dB3 = dB * dB * dB;
        av[i] = pk2(csN * dA3 * a[f0 + 2 * i], csN * dB3 * a[f0 + 2 * i + 1]);
        bv[i] = pk2(csN * dA3 * 1000.f * MFR * b[f0 + 2 * i],
                    csN * dB3 * 1000.f * MFR * b[f0 + 2 * i + 1]);
        dv[i] = pk2(dA, dB);
        u[i] = 0ull;
    }
    float suma = 0.f, sumb = 0.f, a1c = 0.f, b1c = 0.f, a2c = 0.f, b2c = 0.f;
#pragma unroll
    for (int n = 0; n < NN; n++) {
        const float dn = 1.f - ds[n];
        const float An = csN * a[n];
        const float Bn = csN * 1000.f * MFR * b[n];
        suma += a[n]; sumb += b[n];
        a1c += dn * An;        b1c += dn * Bn;
        a2c += dn * dn * An;   b2c += dn * dn * Bn;
    }
    const float ca = suma * csN;
    const float cb = 1000.f * MFR * sumb * csN;
    const float c0 = -gb[0] * invmc;
    const float q0 = pc[0] * pc[0], q1 = pc[1] * pc[1], q2 = pc[2] * pc[2],
                q3 = pc[3] * pc[3], q4 = pc[4] * pc[4];

    const float4* cp4 = g_cur4 + row;
    float* op = out + row + (size_t)sub * BB;
    float th = 0.f, M1 = 0.f, M2 = 0.f;

    float4 q0buf = __ldg(cp4);
    float4 q1buf = __ldg(cp4 + BB);

#define STEP(CUR, J)                                                        \
    {                                                                       \
        const float cur_ = (CUR);                                           \
        const float pre_ = fmaf(cur_, ca, c0);                              \
        /* own d^3-weighted partial: u IS already d^3*V */                  \
        u64 s_ = add2_(u[0], u[1]);                                         \
        float sx_, sy_; upk2(s_, sx_, sy_);                                 \
        const float part_ = sx_ + sy_;                                      \
        asm volatile("st.shared.f32 [%0], %1;" :: "r"(ast), "f"(part_)      \
                     : "memory");                                           \
        /* ---- th critical path (uses carried M1 = M_1[t-1]) ---- */       \
        const float x_ = fmaf(th, cb, M1 + pre_);                           \
        const float x2_ = x_ * x_;                                          \
        const float u01_ = fmaf(q1, x_, q0);                                \
        const float u34_ = fmaf(q4, x_, q3);                                \
        const float w1s_ = fmaf(q2, x2_, u01_);                             \
        const float x3_ = x_ * x2_;                                         \
        float p_ = fmaf(u34_, x3_, w1s_);                                   \
        p_ = fmaxf(p_, 0.f);                                                \
        const float thn_ = tanh_a(p_);                                      \
        /* single LDS.128 gather of all 4 partials */                       \
        float r0_, r1_, r2_, r3_;                                           \
        asm volatile("ld.shared.v4.f32 {%0,%1,%2,%3}, [%4];"                \
                     : "=f"(r0_), "=f"(r1_), "=f"(r2_), "=f"(r3_)           \
                     : "r"(ald) : "memory");                                \
        const float R3_ = (r0_ + r1_) + (r2_ + r3_);                        \
        /* ---- moment pipeline ---- */                                     \
        const float M1n_ = M2 + fmaf(th, b1c, cur_ * a1c);                  \
        const float M2n_ = R3_ + fmaf(th, b2c, cur_ * a2c);                 \
        /* ---- u-state update with OLD th ---- */                          \
        const u64 cur2_ = pk2(cur_, cur_);                                  \
        const u64 th2_  = pk2(th, th);                                      \
        u[0] = fma2_(dv[0], u[0], fma2_(th2_, bv[0], mul2_(cur2_, av[0]))); \
        u[1] = fma2_(dv[1], u[1], fma2_(th2_, bv[1], mul2_(cur2_, av[1]))); \
        M1 = M1n_; M2 = M2n_;                                               \
        if ((J) == sub) outv = MFR * thn_;                                  \
        th = thn_;                                                          \
    }

    for (int tq = 0; tq < TQ; tq += 2) {
        float outv = 0.f;
        {
            const float4 q = q0buf;
            q0buf = __ldg(cp4 + (size_t)(tq + 2) * BB);
            STEP(q.x, 0) STEP(q.y, 1) STEP(q.z, 2) STEP(q.w, 3)
            op[(size_t)tq * (4 * BB)] = outv;
        }
        {
            const float4 q = q1buf;
            q1buf = __ldg(cp4 + (size_t)(tq + 3) * BB);
            STEP(q.x, 0) STEP(q.y, 1) STEP(q.z, 2) STEP(q.w, 3)
            op[(size_t)(tq + 1) * (4 * BB)] = outv;
        }
    }
#undef STEP
}

extern "C" void kernel_launch(void* const* d_in, const int* in_sizes, int n_in,
                              void* d_out, int out_size) {
    const float* currents = (const float*)d_in[0];
    const float* a   = (const float*)d_in[1];
    const float* b   = (const float*)d_in[2];
    const float* pc  = (const float*)d_in[3];
    const float* gb  = (const float*)d_in[4];
    const float* ds  = (const float*)d_in[5];
    const float* mc  = (const float*)d_in[6];
    const float* mfr = (const float*)d_in[7];
    float* out = (float*)d_out;

    dim3 tb(32, 8), tg(TT / 32, BB / 32);
    transpose_kernel<<<tg, tb>>>(currents);
    gfr_kernel<<<(4 * BB) / 128, 128>>>(a, b, pc, gb, ds, mc, mfr, out);
}